// round 9
// baseline (speedup 1.0000x reference)
#include <cuda_runtime.h>
#include <math.h>

#define N_NODES 163842
#define N_EDGES 983040

// ---------------- device scratch (globals: no allocation allowed) ----------------
__device__ int    g_is64;
__device__ int    g_count[N_NODES];
__device__ int    g_rowptr[N_NODES + 1];
__device__ int    g_cursor[N_NODES];
__device__ int    g_bsums[256];
__device__ int    g_ssrc[N_EDGES];
__device__ __align__(16) float2 g_sea[N_EDGES];
__device__ __align__(16) float4 g_gaussL[3][N_EDGES];
__device__ float  g_invdeg[N_NODES];
__device__ __align__(16) float g_A[(size_t)N_NODES * 192];   // max 3*CIN = 192 (layer 2)
__device__ __align__(16) float g_hb0[(size_t)N_NODES * 64];
__device__ __align__(16) float g_hb1[(size_t)N_NODES * 64];

// ---------------- edge_index dtype probe ----------------
// Reference declares int64, but default-config JAX canonicalizes to int32.
// Interpret the first N_EDGES 8-byte words (= int32 buffer's full size, or the
// src half of an int64 buffer) as int64: any value outside [0, N_NODES) => int32.
__global__ void detect_init_kernel() { g_is64 = 1; }

__global__ void detect_kernel(const long long* __restrict__ ei) {
    int e = blockIdx.x * blockDim.x + threadIdx.x;
    if (e < N_EDGES) {
        long long v = ei[e];
        if (v < 0 || v >= (long long)N_NODES) g_is64 = 0;   // all writers store 0: race-free
    }
}

__device__ __forceinline__ int load_idx(const void* ei, int is64, int pos) {
    return is64 ? (int)((const long long*)ei)[pos] : ((const int*)ei)[pos];
}

// ---------------- sort / degree kernels ----------------
__global__ void zero_counts_kernel() {
    int i = blockIdx.x * blockDim.x + threadIdx.x;
    if (i < N_NODES) { g_count[i] = 0; g_cursor[i] = 0; }
}

__global__ void hist_kernel(const void* __restrict__ ei) {
    int e = blockIdx.x * blockDim.x + threadIdx.x;
    if (e >= N_EDGES) return;
    int d = load_idx(ei, g_is64, N_EDGES + e);
    if ((unsigned)d < (unsigned)N_NODES) atomicAdd(&g_count[d], 1);
}

__global__ void scan1_kernel() {
    int t = threadIdx.x, b = blockIdx.x;
    int i = b * 1024 + t;
    int v = (i < N_NODES) ? g_count[i] : 0;
    int lane = t & 31, wid = t >> 5;
    int x = v;
#pragma unroll
    for (int d = 1; d < 32; d <<= 1) { int y = __shfl_up_sync(0xffffffffu, x, d); if (lane >= d) x += y; }
    __shared__ int ws[32];
    if (lane == 31) ws[wid] = x;
    __syncthreads();
    if (wid == 0) {
        int y = ws[lane];
#pragma unroll
        for (int d = 1; d < 32; d <<= 1) { int z = __shfl_up_sync(0xffffffffu, y, d); if (lane >= d) y += z; }
        ws[lane] = y;
    }
    __syncthreads();
    int incl = x + (wid > 0 ? ws[wid - 1] : 0);
    if (i < N_NODES) g_rowptr[i] = incl - v;      // block-local exclusive
    if (t == 1023) g_bsums[b] = incl;             // block total
}

__global__ void scan2_kernel(int nb) {
    int t = threadIdx.x;
    int v = (t < nb) ? g_bsums[t] : 0;
    int lane = t & 31, wid = t >> 5;
    int x = v;
#pragma unroll
    for (int d = 1; d < 32; d <<= 1) { int y = __shfl_up_sync(0xffffffffu, x, d); if (lane >= d) x += y; }
    __shared__ int ws[32];
    if (lane == 31) ws[wid] = x;
    __syncthreads();
    if (wid == 0) {
        int y = ws[lane];
#pragma unroll
        for (int d = 1; d < 32; d <<= 1) { int z = __shfl_up_sync(0xffffffffu, y, d); if (lane >= d) y += z; }
        ws[lane] = y;
    }
    __syncthreads();
    int incl = x + (wid > 0 ? ws[wid - 1] : 0);
    if (t < nb) g_bsums[t] = incl - v;            // exclusive block offsets
}

__global__ void scan3_kernel() {
    int i = blockIdx.x * blockDim.x + threadIdx.x;
    if (i < N_NODES) {
        g_rowptr[i] += g_bsums[i >> 10];
        int c = g_count[i];
        g_invdeg[i] = 1.0f / (float)(c > 1 ? c : 1);
    }
    if (i == 0) g_rowptr[N_NODES] = N_EDGES;
}

__global__ void scatter_kernel(const void* __restrict__ ei, const float2* __restrict__ ea) {
    int e = blockIdx.x * blockDim.x + threadIdx.x;
    if (e >= N_EDGES) return;
    int is64 = g_is64;
    int d = load_idx(ei, is64, N_EDGES + e);
    if ((unsigned)d >= (unsigned)N_NODES) return;
    int s = load_idx(ei, is64, e);
    if ((unsigned)s >= (unsigned)N_NODES) s = 0;
    int pos = g_rowptr[d] + atomicAdd(&g_cursor[d], 1);
    g_ssrc[pos] = s;
    g_sea[pos] = ea[e];
}

// ---------------- edge Gaussian weights, all 3 layers fused ----------------
__global__ void gauss_kernel(const float* __restrict__ mu0, const float* __restrict__ s0,
                             const float* __restrict__ mu1, const float* __restrict__ s1,
                             const float* __restrict__ mu2, const float* __restrict__ s2)
{
    int e = blockIdx.x * blockDim.x + threadIdx.x;
    if (e >= N_EDGES) return;
    float2 p = g_sea[e];
    const float* mus[3] = {mu0, mu1, mu2};
    const float* sgs[3] = {s0, s1, s2};
#pragma unroll
    for (int l = 0; l < 3; l++) {
        float gk[3];
#pragma unroll
        for (int k = 0; k < 3; k++) {
            float mx = __ldg(&mus[l][k * 2]), my = __ldg(&mus[l][k * 2 + 1]);
            float sx = __ldg(&sgs[l][k * 2]), sy = __ldg(&sgs[l][k * 2 + 1]);
            float dx = p.x - mx, dy = p.y - my;
            float t = dx * dx / (1e-15f + sx * sx) + dy * dy / (1e-15f + sy * sy);
            gk[k] = expf(-0.5f * t);
        }
        g_gaussL[l][e] = make_float4(gk[0], gk[1], gk[2], 0.0f);
    }
}

// ---------------- aggregation: g_A[d, k*CIN + c] = invdeg[d] * sum_{e->d} gauss[e,k]*x[src,c] ----------------
__device__ __forceinline__ const float* pick_src(int sel, const float* x) {
    return sel == 0 ? x : (sel == 1 ? (const float*)g_hb0 : (const float*)g_hb1);
}

// CIN = 64 specialization: lane handles 2 channels via float2
__global__ void __launch_bounds__(256) agg64_kernel(const float* __restrict__ xin, int xsel, int layer) {
    int w = (blockIdx.x * blockDim.x + threadIdx.x) >> 5;
    int lane = threadIdx.x & 31;
    if (w >= N_NODES) return;
    const float* X = pick_src(xsel, xin);
    const float4* gauss = g_gaussL[layer];
    int e0 = g_rowptr[w], e1 = g_rowptr[w + 1];
    float a0x = 0.f, a0y = 0.f, a1x = 0.f, a1y = 0.f, a2x = 0.f, a2y = 0.f;
    const float2* X2 = (const float2*)X;
    for (int e = e0; e < e1; ++e) {
        int s = g_ssrc[e];
        if ((unsigned)s >= (unsigned)N_NODES) s = 0;
        float4 gq = gauss[e];
        float2 xv = X2[(size_t)s * 32 + lane];
        a0x = fmaf(gq.x, xv.x, a0x); a0y = fmaf(gq.x, xv.y, a0y);
        a1x = fmaf(gq.y, xv.x, a1x); a1y = fmaf(gq.y, xv.y, a1y);
        a2x = fmaf(gq.z, xv.x, a2x); a2y = fmaf(gq.z, xv.y, a2y);
    }
    float id = g_invdeg[w];
    float2* A2 = (float2*)g_A;
    size_t base = (size_t)w * 96;
    A2[base + lane]      = make_float2(a0x * id, a0y * id);
    A2[base + 32 + lane] = make_float2(a1x * id, a1y * id);
    A2[base + 64 + lane] = make_float2(a2x * id, a2y * id);
}

// CIN <= 32: lane handles one channel
template <int CIN>
__global__ void __launch_bounds__(256) aggS_kernel(const float* __restrict__ xin, int xsel, int layer) {
    int w = (blockIdx.x * blockDim.x + threadIdx.x) >> 5;
    int lane = threadIdx.x & 31;
    if (w >= N_NODES) return;
    const float* X = pick_src(xsel, xin);
    const float4* gauss = g_gaussL[layer];
    int e0 = g_rowptr[w], e1 = g_rowptr[w + 1];
    float a0 = 0.f, a1 = 0.f, a2 = 0.f;
    for (int e = e0; e < e1; ++e) {
        int s = g_ssrc[e];
        if ((unsigned)s >= (unsigned)N_NODES) s = 0;
        float4 gq = gauss[e];
        float xv = (lane < CIN) ? X[(size_t)s * CIN + lane] : 0.f;
        a0 = fmaf(gq.x, xv, a0);
        a1 = fmaf(gq.y, xv, a1);
        a2 = fmaf(gq.z, xv, a2);
    }
    if (lane < CIN) {
        float id = g_invdeg[w];
        size_t base = (size_t)w * (3 * CIN);
        g_A[base + lane]           = a0 * id;
        g_A[base + CIN + lane]     = a1 * id;
        g_A[base + 2 * CIN + lane] = a2 * id;
    }
}

// ---------------- fused GEMM + root + bias + relu (K-chunked, static smem <=48KB) ----------------
// out[n, o] = relu( sum_k A[n,k]*Wg[k,o] + sum_c X[n,c]*root[c,o] + b[o] )
// Tile: 64 nodes x COUT, 256 threads, thread = 4 nodes x (COUT/16) cols. KC k-rows per chunk.
template <int CIN, int COUT, int KC>
__global__ void __launch_bounds__(256) gemm_kernel(
    const float* __restrict__ xin, int xsel, int osel,
    const float* __restrict__ g, const float* __restrict__ root,
    const float* __restrict__ bias)
{
    constexpr int K3 = 3 * CIN;
    constexpr int KTOT = 4 * CIN;
    constexpr int NCH = KTOT / KC;
    constexpr int PADA = KC + 4;
    constexpr int CPT = COUT / 16;
    __shared__ __align__(16) float As[64 * PADA];
    __shared__ __align__(16) float Ws[KC * COUT];
    const float* X = pick_src(xsel, xin);
    float* out = (osel == 1) ? (float*)g_hb0 : (float*)g_hb1;
    const int tid = threadIdx.x;
    const int bn0 = blockIdx.x * 64;
    const int tx = tid & 15, ty = tid >> 4;

    float acc[4][CPT];
#pragma unroll
    for (int i = 0; i < 4; i++)
#pragma unroll
        for (int j = 0; j < CPT; j++) acc[i][j] = 0.f;

    for (int c = 0; c < NCH; ++c) {
        const int k0 = c * KC;
        // weights: rows [0,3*CIN) from g (k-major blocks of Cout), rows [3*CIN,4*CIN) from root
        for (int i = tid; i < KC * COUT; i += 256) {
            int r = i / COUT, o = i - r * COUT;
            int kg = k0 + r;
            float wv;
            if (kg < K3) { int k = kg / CIN, cc = kg - k * CIN; wv = g[cc * (3 * COUT) + k * COUT + o]; }
            else         { int cc = kg - K3;                    wv = root[cc * COUT + o]; }
            Ws[i] = wv;
        }
        // A-tile rows: [0,K3) from g_A, [K3,KTOT) from X
        for (int i = tid; i < 64 * KC; i += 256) {
            int nn = i / KC, kk = i - nn * KC;
            int kg = k0 + kk;
            int gn = bn0 + nn;
            float v = 0.f;
            if (gn < N_NODES)
                v = (kg < K3) ? g_A[(size_t)gn * K3 + kg] : X[(size_t)gn * CIN + (kg - K3)];
            As[nn * PADA + kk] = v;
        }
        __syncthreads();

#pragma unroll 4
        for (int k = 0; k < KC; k += 4) {
            float a_[4][4];
#pragma unroll
            for (int i = 0; i < 4; i++) {
                float4 a4 = *reinterpret_cast<const float4*>(&As[(tx + i * 16) * PADA + k]);
                a_[i][0] = a4.x; a_[i][1] = a4.y; a_[i][2] = a4.z; a_[i][3] = a4.w;
            }
#pragma unroll
            for (int kk = 0; kk < 4; kk++) {
                float wv[CPT];
                if (CPT == 4) {
                    float4 w4 = *reinterpret_cast<const float4*>(&Ws[(k + kk) * COUT + ty * 4]);
                    wv[0] = w4.x; wv[1] = w4.y; wv[2] = w4.z; wv[3] = w4.w;
                } else {
                    float2 w2 = *reinterpret_cast<const float2*>(&Ws[(k + kk) * COUT + ty * 2]);
                    wv[0] = w2.x; wv[1] = w2.y;
                }
#pragma unroll
                for (int i = 0; i < 4; i++)
#pragma unroll
                    for (int j = 0; j < CPT; j++) acc[i][j] = fmaf(a_[i][kk], wv[j], acc[i][j]);
            }
        }
        __syncthreads();
    }

#pragma unroll
    for (int i = 0; i < 4; i++) {
        int gn = bn0 + tx + i * 16;
        if (gn < N_NODES) {
#pragma unroll
            for (int j = 0; j < CPT; j++) {
                float v = acc[i][j] + __ldg(&bias[ty * CPT + j]);
                out[(size_t)gn * COUT + ty * CPT + j] = fmaxf(v, 0.f);
            }
        }
    }
}

// ---------------- final FC (64->2) + log_softmax ----------------
__global__ void __launch_bounds__(256) final_kernel(
    const float* __restrict__ fw, const float* __restrict__ fb, float* __restrict__ out)
{
    int w = (blockIdx.x * blockDim.x + threadIdx.x) >> 5;
    int lane = threadIdx.x & 31;
    if (w >= N_NODES) return;
    float h0 = g_hb0[(size_t)w * 64 + lane];
    float h1 = g_hb0[(size_t)w * 64 + 32 + lane];
    float a0 = h0 * __ldg(&fw[2 * lane])       + h1 * __ldg(&fw[2 * (lane + 32)]);
    float a1 = h0 * __ldg(&fw[2 * lane + 1])   + h1 * __ldg(&fw[2 * (lane + 32) + 1]);
#pragma unroll
    for (int d = 16; d > 0; d >>= 1) {
        a0 += __shfl_xor_sync(0xffffffffu, a0, d);
        a1 += __shfl_xor_sync(0xffffffffu, a1, d);
    }
    if (lane == 0) {
        float l0 = a0 + __ldg(&fb[0]), l1 = a1 + __ldg(&fb[1]);
        float m = fmaxf(l0, l1);
        float lse = m + logf(expf(l0 - m) + expf(l1 - m));
        out[(size_t)w * 2]     = l0 - lse;
        out[(size_t)w * 2 + 1] = l1 - lse;
    }
}

// ---------------- launch (kernel launches ONLY — no other CUDA API calls) ----------------
extern "C" void kernel_launch(void* const* d_in, const int* in_sizes, int n_in,
                              void* d_out, int out_size)
{
    const float* x  = (const float*)d_in[0];
    const void*  ei = d_in[1];                     // int32 or int64 (probed on device)
    const float2* ea = (const float2*)d_in[2];
    const float* g0 = (const float*)d_in[3],  *mu0 = (const float*)d_in[4],  *s0 = (const float*)d_in[5],
               *r0 = (const float*)d_in[6],  *b0 = (const float*)d_in[7];
    const float* g1 = (const float*)d_in[8],  *mu1 = (const float*)d_in[9],  *s1 = (const float*)d_in[10],
               *r1 = (const float*)d_in[11], *b1 = (const float*)d_in[12];
    const float* g2 = (const float*)d_in[13], *mu2 = (const float*)d_in[14], *s2 = (const float*)d_in[15],
               *r2 = (const float*)d_in[16], *b2 = (const float*)d_in[17];
    const float* fw = (const float*)d_in[18], *fb = (const float*)d_in[19];
    float* out = (float*)d_out;

    const int NB = (N_NODES + 255) / 256;
    const int EB = (N_EDGES + 255) / 256;
    const int WB = (N_NODES + 7) / 8;       // warp-per-node, 8 warps/block
    const int GB = (N_NODES + 63) / 64;     // gemm tiles

    // --- probe edge_index dtype ---
    detect_init_kernel<<<1, 1>>>();
    detect_kernel<<<EB, 256>>>((const long long*)ei);

    // --- build CSR by dst (shared across layers) ---
    zero_counts_kernel<<<NB, 256>>>();
    hist_kernel<<<EB, 256>>>(ei);
    scan1_kernel<<<161, 1024>>>();
    scan2_kernel<<<1, 1024>>>(161);
    scan3_kernel<<<NB, 256>>>();
    scatter_kernel<<<EB, 256>>>(ei, ea);

    // --- edge gaussians for all 3 layers ---
    gauss_kernel<<<EB, 256>>>(mu0, s0, mu1, s1, mu2, s2);

    // --- layer 0: 22 -> 32 (x -> hb0) ---
    aggS_kernel<22><<<WB, 256>>>(x, 0, 0);
    gemm_kernel<22, 32, 88><<<GB, 256>>>(x, 0, 1, g0, r0, b0);

    // --- layer 1: 32 -> 64 (hb0 -> hb1) ---
    aggS_kernel<32><<<WB, 256>>>(nullptr, 1, 1);
    gemm_kernel<32, 64, 64><<<GB, 256>>>(nullptr, 1, 2, g1, r1, b1);

    // --- layer 2: 64 -> 64 (hb1 -> hb0) ---
    agg64_kernel<<<WB, 256>>>(nullptr, 2, 2);
    gemm_kernel<64, 64, 64><<<GB, 256>>>(nullptr, 2, 1, g2, r2, b2);

    // --- final FC + log_softmax ---
    final_kernel<<<WB, 256>>>(fw, fb, out);
}